// round 14
// baseline (speedup 1.0000x reference)
#include <cuda_runtime.h>
#include <math.h>
#include <stdint.h>

#define B_ 2
#define S_ 2048
#define DM_ 1024
#define TD_ 1024
#define H_ 16
#define HD_ 64

// ---------------- scratch (static __device__: no allocation) ----------------
__device__ float g_qkv[(size_t)B_ * S_ * 3 * TD_];       // [B*S, 3072]
__device__ float g_q[(size_t)B_ * H_ * S_ * HD_];        // [B,H,S,HD] (tf32-rounded)
__device__ float g_k[(size_t)B_ * H_ * S_ * HD_];        // (tf32-rounded)
__device__ float g_v[(size_t)B_ * H_ * S_ * HD_];        // (tf32-rounded)
__device__ float g_attn[(size_t)B_ * S_ * TD_];          // [B*S, 1024] (tf32-rounded)
__device__ float g_qt[(size_t)B_ * S_ * DM_];            // tf32-rounded query
__device__ float g_wi[(size_t)3 * TD_ * DM_];            // tf32-rounded W_in
__device__ float g_wo[(size_t)DM_ * TD_];                // tf32-rounded W_out
__device__ int   g_len[B_];

// ---------------- helpers ----------------
__device__ __forceinline__ float tf32r(float x) {
    uint32_t u;
    asm("cvt.rna.tf32.f32 %0, %1;" : "=r"(u) : "f"(x));
    return __uint_as_float(u);
}

__device__ __forceinline__ float ex2f(float x) {
    float y;
    asm("ex2.approx.f32 %0, %1;" : "=f"(y) : "f"(x));
    return y;
}

__device__ __forceinline__ void mma_tf32(float c[4],
                                         uint32_t a0, uint32_t a1, uint32_t a2, uint32_t a3,
                                         uint32_t b0, uint32_t b1) {
    asm volatile(
        "mma.sync.aligned.m16n8k8.row.col.f32.tf32.tf32.f32 "
        "{%0,%1,%2,%3}, {%4,%5,%6,%7}, {%8,%9}, {%0,%1,%2,%3};"
        : "+f"(c[0]), "+f"(c[1]), "+f"(c[2]), "+f"(c[3])
        : "r"(a0), "r"(a1), "r"(a2), "r"(a3), "r"(b0), "r"(b1));
}

__device__ __forceinline__ void cpa16(float* s, const float* g) {
    uint32_t sa = (uint32_t)__cvta_generic_to_shared(s);
    asm volatile("cp.async.cg.shared.global [%0], [%1], 16;" :: "r"(sa), "l"(g));
}
#define CP_COMMIT() asm volatile("cp.async.commit_group;")
#define CP_WAIT0()  asm volatile("cp.async.wait_group 0;")

// ---------------- fused elementwise tf32 pre-round (3 tensors, 1 launch) ----
#define CVT_N1 (B_ * S_ * DM_ / 4)        // query float4s
#define CVT_N2 (3 * TD_ * DM_ / 4)        // W_in float4s
#define CVT_N3 (DM_ * TD_ / 4)            // W_out float4s
#define CVT_TOTAL (CVT_N1 + CVT_N2 + CVT_N3)

__global__ void __launch_bounds__(256) cvt3(const float* __restrict__ q,
                                            const float* __restrict__ wi,
                                            const float* __restrict__ wo) {
    int i = blockIdx.x * 256 + threadIdx.x;
    if (i >= CVT_TOTAL) return;
    const float4* s;
    float4* d;
    int j;
    if (i < CVT_N1)                 { s = (const float4*)q;  d = (float4*)g_qt; j = i; }
    else if (i < CVT_N1 + CVT_N2)   { s = (const float4*)wi; d = (float4*)g_wi; j = i - CVT_N1; }
    else                            { s = (const float4*)wo; d = (float4*)g_wo; j = i - CVT_N1 - CVT_N2; }
    float4 t = s[j];
    d[j] = make_float4(tf32r(t.x), tf32r(t.y), tf32r(t.z), tf32r(t.w));
}

// ---------------- lengths from padding mask (dtype-sniffing) ----------------
__global__ void lengths_kernel(const unsigned char* __restrict__ mask) {
    int tid = threadIdx.x;
    if (tid < B_) g_len[tid] = 0;
    __syncthreads();
    int mode;
    if (mask[1] != 0) mode = 0;                                  // 1-byte bool
    else if (mask[2] == 0x80 && mask[3] == 0x3f) mode = 3;       // float32
    else if (mask[4] != 0) mode = 1;                             // int32
    else mode = 2;                                               // int64
    int c0 = 0, c1 = 0;
    for (int i = tid; i < B_ * S_; i += blockDim.x) {
        bool v;
        switch (mode) {
            case 0:  v = mask[i] != 0; break;
            case 1:  v = ((const int*)mask)[i] != 0; break;
            case 2:  v = ((const long long*)mask)[i] != 0LL; break;
            default: v = ((const float*)mask)[i] != 0.0f; break;
        }
        if (i < S_) c0 += v ? 1 : 0; else c1 += v ? 1 : 0;
    }
    if (c0) atomicAdd(&g_len[0], c0);
    if (c1) atomicAdd(&g_len[1], c1);
}

// ---------------- NT tf32 GEMM, cp.async double-buffered ----------------
// Inputs pre-rounded to tf32 -> no cvt in the inner loop. (R6-proven config.)
#define GEMM_SMEM_FLOATS (4 * 128 * 36)
#define GEMM_SMEM_BYTES  (GEMM_SMEM_FLOATS * 4)

__global__ void __launch_bounds__(256) gemm_tf32(const float* __restrict__ A,
                                                 const float* __restrict__ Bm,
                                                 float* __restrict__ C,
                                                 int M, int N, int K) {
    extern __shared__ float sm[];
    float* As = sm;                    // [2][128][36]
    float* Bs = sm + 2 * 128 * 36;     // [2][128][36]
    const int tid = threadIdx.x, lane = tid & 31, warp = tid >> 5;
    const int wm = warp >> 2, wn = warp & 3;
    const int qr = lane >> 2, qc = lane & 3;
    const int m0 = blockIdx.y * 128, n0 = blockIdx.x * 128;

    float acc[4][4][4];
#pragma unroll
    for (int mi = 0; mi < 4; mi++)
#pragma unroll
        for (int ni = 0; ni < 4; ni++)
#pragma unroll
            for (int e = 0; e < 4; e++) acc[mi][ni][e] = 0.f;

    const int nkt = K >> 5;
#pragma unroll
    for (int i = 0; i < 4; i++) {
        int idx = tid + i * 256;
        int r = idx >> 3, s = (idx & 7) * 4;
        cpa16(As + r * 36 + s, A  + (size_t)(m0 + r) * K + s);
        cpa16(Bs + r * 36 + s, Bm + (size_t)(n0 + r) * K + s);
    }
    CP_COMMIT();

    for (int kt = 0; kt < nkt; kt++) {
        const int buf = kt & 1;
        CP_WAIT0();
        __syncthreads();
        if (kt + 1 < nkt) {
            const int ko = (kt + 1) * 32, nb = buf ^ 1;
#pragma unroll
            for (int i = 0; i < 4; i++) {
                int idx = tid + i * 256;
                int r = idx >> 3, s = (idx & 7) * 4;
                cpa16(As + (nb * 128 + r) * 36 + s, A  + (size_t)(m0 + r) * K + ko + s);
                cpa16(Bs + (nb * 128 + r) * 36 + s, Bm + (size_t)(n0 + r) * K + ko + s);
            }
        }
        CP_COMMIT();
        const float* Ab = As + buf * 128 * 36;
        const float* Bb = Bs + buf * 128 * 36;
#pragma unroll
        for (int ks = 0; ks < 4; ks++) {
            const int k = ks * 8 + qc;
            uint32_t af[4][4];
#pragma unroll
            for (int mi = 0; mi < 4; mi++) {
                const float* ar = Ab + (wm * 64 + mi * 16 + qr) * 36;
                af[mi][0] = __float_as_uint(ar[k]);
                af[mi][1] = __float_as_uint(ar[8 * 36 + k]);
                af[mi][2] = __float_as_uint(ar[k + 4]);
                af[mi][3] = __float_as_uint(ar[8 * 36 + k + 4]);
            }
#pragma unroll
            for (int ni = 0; ni < 4; ni++) {
                const float* br = Bb + (wn * 32 + ni * 8 + qr) * 36;
                uint32_t b0 = __float_as_uint(br[k]);
                uint32_t b1 = __float_as_uint(br[k + 4]);
#pragma unroll
                for (int mi = 0; mi < 4; mi++)
                    mma_tf32(acc[mi][ni], af[mi][0], af[mi][1], af[mi][2], af[mi][3], b0, b1);
            }
        }
    }

#pragma unroll
    for (int mi = 0; mi < 4; mi++) {
        int r = m0 + wm * 64 + mi * 16 + qr;
#pragma unroll
        for (int ni = 0; ni < 4; ni++) {
            int c = n0 + wn * 32 + ni * 8 + qc * 2;
            *(float2*)&C[(size_t)r * N + c]       = make_float2(acc[mi][ni][0], acc[mi][ni][1]);
            *(float2*)&C[(size_t)(r + 8) * N + c] = make_float2(acc[mi][ni][2], acc[mi][ni][3]);
        }
    }
}

// ---------------- RoPE + scatter, writes tf32-rounded q/k/v ----------------
__global__ void __launch_bounds__(256) rope_kernel(const float* __restrict__ sinb,
                                                   const float* __restrict__ cosb) {
    int idx = blockIdx.x * 256 + threadIdx.x;   // over B*S*H*HD = 4194304
    int d = idx & 63;
    int h = (idx >> 6) & 15;
    int s = (idx >> 10) & (S_ - 1);
    int b = idx >> 21;
    size_t base = ((size_t)(b * S_ + s)) * (3 * TD_) + h * HD_;
    float cv = cosb[s * HD_ + d];
    float sv = sinb[s * HD_ + d];
    int   dp  = (d < 32) ? d + 32 : d - 32;
    float sgn = (d < 32) ? -1.f : 1.f;
    float qv  = g_qkv[base + d],          q2 = g_qkv[base + dp];
    float kv  = g_qkv[base + TD_ + d],    k2 = g_qkv[base + TD_ + dp];
    size_t oidx = (((size_t)(b * H_ + h)) * S_ + s) * HD_ + d;
    g_q[oidx] = tf32r(fmaf(qv, cv, sgn * q2 * sv));
    g_k[oidx] = tf32r(fmaf(kv, cv, sgn * k2 * sv));
    g_v[oidx] = tf32r(g_qkv[base + 2 * TD_ + d]);
}

// ---------------- flash attention (tf32 MMA, exp2-domain softmax) ----------
// 8 warps x 16 q-rows each; warp-local softmax; pi-permuted keys so the QK
// C-fragment == PV A-fragment. Full tiles skip masking entirely.
// Q pre-scaled by (1/8)*log2(e) so scores are in log2 domain -> bare ex2.
#define AT_QS 0
#define AT_KS (128 * 68)
#define AT_VS (AT_KS + 2 * 128 * 68)
#define ATTN_SMEM_FLOATS (AT_VS + 2 * 128 * 72)
#define ATTN_SMEM_BYTES  (ATTN_SMEM_FLOATS * 4)

#define QSCALE (0.125f * 1.4426950408889634f)

__global__ void __launch_bounds__(256, 1) attn_tf32() {
    extern __shared__ float sm[];
    float (*Qs)[68] = (float(*)[68])(sm + AT_QS);
    float* smK = sm + AT_KS;      // [2][128][68]
    float* smV = sm + AT_VS;      // [2][128][72]

    const int qt = (int)gridDim.x - 1 - (int)blockIdx.x;   // heavy CTAs first
    const int bh = blockIdx.y;
    const int b = bh >> 4, h = bh & 15;
    const int len = g_len[b];
    const int qbase = qt * 128;
    const float* qp = g_q + (size_t)bh * S_ * HD_;
    const float* kp = g_k + (size_t)bh * S_ * HD_;
    const float* vp = g_v + (size_t)bh * S_ * HD_;

    const int tid = threadIdx.x, lane = tid & 31, w = tid >> 5;
    const int qr = lane >> 2, qc = lane & 3;
    const int piq = (qr & 1) ? (qr >> 1) + 4 : (qr >> 1);   // pi(qr)

    int nkt = qt + 1;
    int lkt = (len + 127) >> 7;
    if (lkt < nkt) nkt = lkt;

    // prologue: cp.async K/V tile 0 (already tf32-valid bits)
#pragma unroll
    for (int i = 0; i < 8; i++) {
        int idx = tid + i * 256;
        int r = idx >> 4, s = (idx & 15) * 4;
        cpa16(smK + r * 68 + s, kp + (size_t)r * HD_ + s);
        cpa16(smV + r * 72 + s, vp + (size_t)r * HD_ + s);
    }
    CP_COMMIT();

    // Q tile: scale by (1/8)*log2e, re-round to tf32 (once per CTA)
    for (int i = tid; i < 2048; i += 256) {
        int r = i >> 4, d4 = (i & 15) << 2;
        float4 t = *(const float4*)&qp[(size_t)(qbase + r) * HD_ + d4];
        *(float4*)&Qs[r][d4] = make_float4(tf32r(t.x * QSCALE), tf32r(t.y * QSCALE),
                                           tf32r(t.z * QSCALE), tf32r(t.w * QSCALE));
    }

    float m0r = -INFINITY, m1r = -INFINITY, l0 = 0.f, l1 = 0.f;
    float o[8][4];
#pragma unroll
    for (int nd = 0; nd < 8; nd++)
#pragma unroll
        for (int e = 0; e < 4; e++) o[nd][e] = 0.f;

    for (int kt = 0; kt < nkt; kt++) {
        const int buf = kt & 1;
        const int kb = kt * 128;
        CP_WAIT0();
        __syncthreads();
        if (kt + 1 < nkt) {
            const int nb = buf ^ 1, ko = (kt + 1) * 128;
#pragma unroll
            for (int i = 0; i < 8; i++) {
                int idx = tid + i * 256;
                int r = idx >> 4, s = (idx & 15) * 4;
                cpa16(smK + (nb * 128 + r) * 68 + s, kp + (size_t)(ko + r) * HD_ + s);
                cpa16(smV + (nb * 128 + r) * 72 + s, vp + (size_t)(ko + r) * HD_ + s);
            }
        }
        CP_COMMIT();
        const float* Kb = smK + buf * 128 * 68;
        const float* Vb = smV + buf * 128 * 72;

        // ---- QK^T: 16 rows x 128 keys, keys column-permuted by pi ----
        float sf[16][4];
#pragma unroll
        for (int ni = 0; ni < 16; ni++)
#pragma unroll
            for (int e = 0; e < 4; e++) sf[ni][e] = 0.f;

#pragma unroll
        for (int ks = 0; ks < 8; ks++) {
            const int k = ks * 8 + qc;
            const float* ar = Qs[w * 16 + qr];
            uint32_t a0 = __float_as_uint(ar[k]);
            uint32_t a1 = __float_as_uint(ar[8 * 68 + k]);
            uint32_t a2 = __float_as_uint(ar[k + 4]);
            uint32_t a3 = __float_as_uint(ar[8 * 68 + k + 4]);
#pragma unroll
            for (int ni = 0; ni < 16; ni++) {
                const float* kr = Kb + (ni * 8 + piq) * 68;
                uint32_t b0 = __float_as_uint(kr[k]);
                uint32_t b1 = __float_as_uint(kr[k + 4]);
                mma_tf32(sf[ni], a0, a1, a2, a3, b0, b1);
            }
        }

        // ---- row max (masked only on diagonal / len-boundary tiles) ----
        const int rl = qbase + w * 16 + qr, rh = rl + 8;
        float mx0 = -INFINITY, mx1 = -INFINITY;
        if (kt == qt || kb + 128 > len) {
#pragma unroll
            for (int ni = 0; ni < 16; ni++) {
                int k0 = kb + ni * 8 + qc, k1 = k0 + 4;
                if (k0 > rl || k0 >= len) sf[ni][0] = -INFINITY;
                if (k1 > rl || k1 >= len) sf[ni][1] = -INFINITY;
                if (k0 > rh || k0 >= len) sf[ni][2] = -INFINITY;
                if (k1 > rh || k1 >= len) sf[ni][3] = -INFINITY;
                mx0 = fmaxf(mx0, fmaxf(sf[ni][0], sf[ni][1]));
                mx1 = fmaxf(mx1, fmaxf(sf[ni][2], sf[ni][3]));
            }
        } else {
#pragma unroll
            for (int ni = 0; ni < 16; ni++) {
                mx0 = fmaxf(mx0, fmaxf(sf[ni][0], sf[ni][1]));
                mx1 = fmaxf(mx1, fmaxf(sf[ni][2], sf[ni][3]));
            }
        }
        mx0 = fmaxf(mx0, __shfl_xor_sync(0xffffffffu, mx0, 1));
        mx0 = fmaxf(mx0, __shfl_xor_sync(0xffffffffu, mx0, 2));
        mx1 = fmaxf(mx1, __shfl_xor_sync(0xffffffffu, mx1, 1));
        mx1 = fmaxf(mx1, __shfl_xor_sync(0xffffffffu, mx1, 2));

        float mn0 = fmaxf(m0r, mx0), mn1 = fmaxf(m1r, mx1);
        float corr0 = ex2f(m0r - mn0), corr1 = ex2f(m1r - mn1);
        m0r = mn0; m1r = mn1;

        // ---- exp2 + row sum; P (tf32-rounded) kept in sf regs ----
        float s0 = 0.f, s1 = 0.f;
#pragma unroll
        for (int ni = 0; ni < 16; ni++) {
            float p0 = ex2f(sf[ni][0] - mn0);
            float p1 = ex2f(sf[ni][1] - mn0);
            float p2 = ex2f(sf[ni][2] - mn1);
            float p3 = ex2f(sf[ni][3] - mn1);
            s0 += p0 + p1; s1 += p2 + p3;
            sf[ni][0] = tf32r(p0); sf[ni][1] = tf32r(p1);
            sf[ni][2] = tf32r(p2); sf[ni][3] = tf32r(p3);
        }
        s0 += __shfl_xor_sync(0xffffffffu, s0, 1);
        s0 += __shfl_xor_sync(0xffffffffu, s0, 2);
        s1 += __shfl_xor_sync(0xffffffffu, s1, 1);
        s1 += __shfl_xor_sync(0xffffffffu, s1, 2);
        l0 = l0 * corr0 + s0;
        l1 = l1 * corr1 + s1;
#pragma unroll
        for (int nd = 0; nd < 8; nd++) {
            o[nd][0] *= corr0; o[nd][1] *= corr0;
            o[nd][2] *= corr1; o[nd][3] *= corr1;
        }

        // ---- O += P V: A-fragment straight from score regs (pi trick) ----
#pragma unroll
        for (int ks2 = 0; ks2 < 16; ks2++) {
            uint32_t a0 = __float_as_uint(sf[ks2][0]);   // (row qr,  key qc)
            uint32_t a1 = __float_as_uint(sf[ks2][2]);   // (row qr+8,key qc)
            uint32_t a2 = __float_as_uint(sf[ks2][1]);   // (row qr,  key qc+4)
            uint32_t a3 = __float_as_uint(sf[ks2][3]);   // (row qr+8,key qc+4)
            const float* v0 = Vb + (ks2 * 8 + qc) * 72;
            const float* v1 = v0 + 4 * 72;
#pragma unroll
            for (int nd = 0; nd < 8; nd++) {
                int dcol = nd * 8 + qr;
                uint32_t b0 = __float_as_uint(v0[dcol]);
                uint32_t b1 = __float_as_uint(v1[dcol]);
                mma_tf32(o[nd], a0, a1, a2, a3, b0, b1);
            }
        }
    }

    // ---- normalize + write tf32-rounded (feeds out-proj GEMM) ----
    const float inv0 = 1.f / l0, inv1 = 1.f / l1;
    const int rl = qbase + w * 16 + qr;
#pragma unroll
    for (int nd = 0; nd < 8; nd++) {
        int c = h * HD_ + nd * 8 + qc * 2;
        *(float2*)&g_attn[((size_t)b * S_ + rl) * TD_ + c] =
            make_float2(tf32r(o[nd][0] * inv0), tf32r(o[nd][1] * inv0));
        *(float2*)&g_attn[((size_t)b * S_ + rl + 8) * TD_ + c] =
            make_float2(tf32r(o[nd][2] * inv1), tf32r(o[nd][3] * inv1));
    }
}

// ---------------- launch ----------------
extern "C" void kernel_launch(void* const* d_in, const int* in_sizes, int n_in,
                              void* d_out, int out_size) {
    const float* query = (const float*)d_in[0];
    const float* W_in  = (const float*)d_in[1];
    const float* W_out = (const float*)d_in[2];
    const float* sinb  = (const float*)d_in[3];
    const float* cosb  = (const float*)d_in[4];
    const unsigned char* mask = (const unsigned char*)d_in[5];
    float* out = (float*)d_out;

    void *p_qkv = nullptr, *p_attn = nullptr, *p_qt = nullptr, *p_wi = nullptr, *p_wo = nullptr;
    cudaGetSymbolAddress(&p_qkv, g_qkv);
    cudaGetSymbolAddress(&p_attn, g_attn);
    cudaGetSymbolAddress(&p_qt, g_qt);
    cudaGetSymbolAddress(&p_wi, g_wi);
    cudaGetSymbolAddress(&p_wo, g_wo);
    cudaFuncSetAttribute(attn_tf32, cudaFuncAttributeMaxDynamicSharedMemorySize,
                         ATTN_SMEM_BYTES);
    cudaFuncSetAttribute(gemm_tf32, cudaFuncAttributeMaxDynamicSharedMemorySize,
                         GEMM_SMEM_BYTES);

    lengths_kernel<<<1, 256>>>(mask);

    // pre-round all GEMM inputs to tf32 in ONE launch
    cvt3<<<(CVT_TOTAL + 255) / 256, 256>>>(query, W_in, W_out);

    // QKV projection: [4096,1024] x [3072,1024]^T -> [4096,3072]
    gemm_tf32<<<dim3(3 * TD_ / 128, B_ * S_ / 128), 256, GEMM_SMEM_BYTES>>>(
        (const float*)p_qt, (const float*)p_wi, (float*)p_qkv, B_ * S_, 3 * TD_, DM_);

    // RoPE + scatter to [B,H,S,HD] (tf32-rounded)
    rope_kernel<<<(B_ * S_ * H_ * HD_) / 256, 256>>>(sinb, cosb);

    // causal flash attention (tf32 tensor-core, exp2-domain softmax)
    attn_tf32<<<dim3(S_ / 128, B_ * H_), 256, ATTN_SMEM_BYTES>>>();

    // output projection: [4096,1024] x [1024,1024]^T -> d_out
    gemm_tf32<<<dim3(DM_ / 128, B_ * S_ / 128), 256, GEMM_SMEM_BYTES>>>(
        (const float*)p_attn, (const float*)p_wo, out, B_ * S_, DM_, TD_);
}

// round 15
// speedup vs baseline: 1.4906x; 1.4906x over previous
#include <cuda_runtime.h>
#include <math.h>
#include <stdint.h>

#define B_ 2
#define S_ 2048
#define DM_ 1024
#define TD_ 1024
#define H_ 16
#define HD_ 64

// ---------------- scratch (static __device__: no allocation) ----------------
__device__ float g_qkv[(size_t)B_ * S_ * 3 * TD_];       // [B*S, 3072]
__device__ float g_q[(size_t)B_ * H_ * S_ * HD_];        // [B,H,S,HD] (tf32-rounded)
__device__ float g_k[(size_t)B_ * H_ * S_ * HD_];        // (tf32-rounded)
__device__ float g_v[(size_t)B_ * H_ * S_ * HD_];        // (tf32-rounded)
__device__ float g_attn[(size_t)B_ * S_ * TD_];          // [B*S, 1024] (tf32-rounded)
__device__ float g_qt[(size_t)B_ * S_ * DM_];            // tf32-rounded query
__device__ float g_wi[(size_t)3 * TD_ * DM_];            // tf32-rounded W_in
__device__ float g_wo[(size_t)DM_ * TD_];                // tf32-rounded W_out
__device__ int   g_len[B_];

// ---------------- helpers ----------------
__device__ __forceinline__ float tf32r(float x) {
    uint32_t u;
    asm("cvt.rna.tf32.f32 %0, %1;" : "=r"(u) : "f"(x));
    return __uint_as_float(u);
}

__device__ __forceinline__ void mma_tf32(float c[4],
                                         uint32_t a0, uint32_t a1, uint32_t a2, uint32_t a3,
                                         uint32_t b0, uint32_t b1) {
    asm volatile(
        "mma.sync.aligned.m16n8k8.row.col.f32.tf32.tf32.f32 "
        "{%0,%1,%2,%3}, {%4,%5,%6,%7}, {%8,%9}, {%0,%1,%2,%3};"
        : "+f"(c[0]), "+f"(c[1]), "+f"(c[2]), "+f"(c[3])
        : "r"(a0), "r"(a1), "r"(a2), "r"(a3), "r"(b0), "r"(b1));
}

__device__ __forceinline__ void cpa16(float* s, const float* g) {
    uint32_t sa = (uint32_t)__cvta_generic_to_shared(s);
    asm volatile("cp.async.cg.shared.global [%0], [%1], 16;" :: "r"(sa), "l"(g));
}
#define CP_COMMIT() asm volatile("cp.async.commit_group;")
#define CP_WAIT0()  asm volatile("cp.async.wait_group 0;")

// ---------------- elementwise tf32 pre-round ----------------
__global__ void __launch_bounds__(256) cvt_tf32(const float* __restrict__ src,
                                                float* __restrict__ dst, int n4) {
    int i = blockIdx.x * 256 + threadIdx.x;
    if (i < n4) {
        float4 t = ((const float4*)src)[i];
        ((float4*)dst)[i] = make_float4(tf32r(t.x), tf32r(t.y), tf32r(t.z), tf32r(t.w));
    }
}

// ---------------- lengths from padding mask (dtype-sniffing) ----------------
__global__ void lengths_kernel(const unsigned char* __restrict__ mask) {
    int tid = threadIdx.x;
    if (tid < B_) g_len[tid] = 0;
    __syncthreads();
    int mode;
    if (mask[1] != 0) mode = 0;                                  // 1-byte bool
    else if (mask[2] == 0x80 && mask[3] == 0x3f) mode = 3;       // float32
    else if (mask[4] != 0) mode = 1;                             // int32
    else mode = 2;                                               // int64
    int c0 = 0, c1 = 0;
    for (int i = tid; i < B_ * S_; i += blockDim.x) {
        bool v;
        switch (mode) {
            case 0:  v = mask[i] != 0; break;
            case 1:  v = ((const int*)mask)[i] != 0; break;
            case 2:  v = ((const long long*)mask)[i] != 0LL; break;
            default: v = ((const float*)mask)[i] != 0.0f; break;
        }
        if (i < S_) c0 += v ? 1 : 0; else c1 += v ? 1 : 0;
    }
    if (c0) atomicAdd(&g_len[0], c0);
    if (c1) atomicAdd(&g_len[1], c1);
}

// ---------------- NT tf32 GEMM, cp.async double-buffered ----------------
// Inputs pre-rounded to tf32 -> no cvt in the inner loop.
#define GEMM_SMEM_FLOATS (4 * 128 * 36)
#define GEMM_SMEM_BYTES  (GEMM_SMEM_FLOATS * 4)

__global__ void __launch_bounds__(256) gemm_tf32(const float* __restrict__ A,
                                                 const float* __restrict__ Bm,
                                                 float* __restrict__ C,
                                                 int M, int N, int K) {
    extern __shared__ float sm[];
    float* As = sm;                    // [2][128][36]
    float* Bs = sm + 2 * 128 * 36;     // [2][128][36]
    const int tid = threadIdx.x, lane = tid & 31, warp = tid >> 5;
    const int wm = warp >> 2, wn = warp & 3;
    const int qr = lane >> 2, qc = lane & 3;
    const int m0 = blockIdx.y * 128, n0 = blockIdx.x * 128;

    float acc[4][4][4];
#pragma unroll
    for (int mi = 0; mi < 4; mi++)
#pragma unroll
        for (int ni = 0; ni < 4; ni++)
#pragma unroll
            for (int e = 0; e < 4; e++) acc[mi][ni][e] = 0.f;

    const int nkt = K >> 5;
#pragma unroll
    for (int i = 0; i < 4; i++) {
        int idx = tid + i * 256;
        int r = idx >> 3, s = (idx & 7) * 4;
        cpa16(As + r * 36 + s, A  + (size_t)(m0 + r) * K + s);
        cpa16(Bs + r * 36 + s, Bm + (size_t)(n0 + r) * K + s);
    }
    CP_COMMIT();

    for (int kt = 0; kt < nkt; kt++) {
        const int buf = kt & 1;
        CP_WAIT0();
        __syncthreads();
        if (kt + 1 < nkt) {
            const int ko = (kt + 1) * 32, nb = buf ^ 1;
#pragma unroll
            for (int i = 0; i < 4; i++) {
                int idx = tid + i * 256;
                int r = idx >> 3, s = (idx & 7) * 4;
                cpa16(As + (nb * 128 + r) * 36 + s, A  + (size_t)(m0 + r) * K + ko + s);
                cpa16(Bs + (nb * 128 + r) * 36 + s, Bm + (size_t)(n0 + r) * K + ko + s);
            }
        }
        CP_COMMIT();
        const float* Ab = As + buf * 128 * 36;
        const float* Bb = Bs + buf * 128 * 36;
#pragma unroll
        for (int ks = 0; ks < 4; ks++) {
            const int k = ks * 8 + qc;
            uint32_t af[4][4];
#pragma unroll
            for (int mi = 0; mi < 4; mi++) {
                const float* ar = Ab + (wm * 64 + mi * 16 + qr) * 36;
                af[mi][0] = __float_as_uint(ar[k]);
                af[mi][1] = __float_as_uint(ar[8 * 36 + k]);
                af[mi][2] = __float_as_uint(ar[k + 4]);
                af[mi][3] = __float_as_uint(ar[8 * 36 + k + 4]);
            }
#pragma unroll
            for (int ni = 0; ni < 4; ni++) {
                const float* br = Bb + (wn * 32 + ni * 8 + qr) * 36;
                uint32_t b0 = __float_as_uint(br[k]);
                uint32_t b1 = __float_as_uint(br[k + 4]);
#pragma unroll
                for (int mi = 0; mi < 4; mi++)
                    mma_tf32(acc[mi][ni], af[mi][0], af[mi][1], af[mi][2], af[mi][3], b0, b1);
            }
        }
    }

#pragma unroll
    for (int mi = 0; mi < 4; mi++) {
        int r = m0 + wm * 64 + mi * 16 + qr;
#pragma unroll
        for (int ni = 0; ni < 4; ni++) {
            int c = n0 + wn * 32 + ni * 8 + qc * 2;
            *(float2*)&C[(size_t)r * N + c]       = make_float2(acc[mi][ni][0], acc[mi][ni][1]);
            *(float2*)&C[(size_t)(r + 8) * N + c] = make_float2(acc[mi][ni][2], acc[mi][ni][3]);
        }
    }
}

// ---------------- RoPE + scatter, writes tf32-rounded q/k/v ----------------
__global__ void __launch_bounds__(256) rope_kernel(const float* __restrict__ sinb,
                                                   const float* __restrict__ cosb) {
    int idx = blockIdx.x * 256 + threadIdx.x;   // over B*S*H*HD = 4194304
    int d = idx & 63;
    int h = (idx >> 6) & 15;
    int s = (idx >> 10) & (S_ - 1);
    int b = idx >> 21;
    size_t base = ((size_t)(b * S_ + s)) * (3 * TD_) + h * HD_;
    float cv = cosb[s * HD_ + d];
    float sv = sinb[s * HD_ + d];
    int   dp  = (d < 32) ? d + 32 : d - 32;
    float sgn = (d < 32) ? -1.f : 1.f;
    float qv  = g_qkv[base + d],          q2 = g_qkv[base + dp];
    float kv  = g_qkv[base + TD_ + d],    k2 = g_qkv[base + TD_ + dp];
    size_t oidx = (((size_t)(b * H_ + h)) * S_ + s) * HD_ + d;
    g_q[oidx] = tf32r(fmaf(qv, cv, sgn * q2 * sv));
    g_k[oidx] = tf32r(fmaf(kv, cv, sgn * k2 * sv));
    g_v[oidx] = tf32r(g_qkv[base + 2 * TD_ + d]);
}

// ---------------- flash attention v3 (tf32 MMA, no in-loop cvt) ----------------
// 8 warps x 16 q-rows each; warp-local softmax; pi-permuted keys so the QK
// C-fragment == PV A-fragment. Full tiles skip masking entirely.
#define AT_QS 0
#define AT_KS (128 * 68)
#define AT_VS (AT_KS + 2 * 128 * 68)
#define ATTN_SMEM_FLOATS (AT_VS + 2 * 128 * 72)
#define ATTN_SMEM_BYTES  (ATTN_SMEM_FLOATS * 4)

__global__ void __launch_bounds__(256, 1) attn_tf32() {
    extern __shared__ float sm[];
    float (*Qs)[68] = (float(*)[68])(sm + AT_QS);
    float* smK = sm + AT_KS;      // [2][128][68]
    float* smV = sm + AT_VS;      // [2][128][72]

    const int qt = (int)gridDim.x - 1 - (int)blockIdx.x;   // heavy CTAs first
    const int bh = blockIdx.y;
    const int b = bh >> 4, h = bh & 15;
    const int len = g_len[b];
    const int qbase = qt * 128;
    const float* qp = g_q + (size_t)bh * S_ * HD_;
    const float* kp = g_k + (size_t)bh * S_ * HD_;
    const float* vp = g_v + (size_t)bh * S_ * HD_;

    const int tid = threadIdx.x, lane = tid & 31, w = tid >> 5;
    const int qr = lane >> 2, qc = lane & 3;
    const int piq = (qr & 1) ? (qr >> 1) + 4 : (qr >> 1);   // pi(qr)

    int nkt = qt + 1;
    int lkt = (len + 127) >> 7;
    if (lkt < nkt) nkt = lkt;

    // prologue: cp.async K/V tile 0 (already tf32-valid bits)
#pragma unroll
    for (int i = 0; i < 8; i++) {
        int idx = tid + i * 256;
        int r = idx >> 4, s = (idx & 15) * 4;
        cpa16(smK + r * 68 + s, kp + (size_t)r * HD_ + s);
        cpa16(smV + r * 72 + s, vp + (size_t)r * HD_ + s);
    }
    CP_COMMIT();

    // Q tile: scale by 1/8 (exact power of 2 -> stays tf32-valid)
    for (int i = tid; i < 2048; i += 256) {
        int r = i >> 4, d4 = (i & 15) << 2;
        float4 t = *(const float4*)&qp[(size_t)(qbase + r) * HD_ + d4];
        *(float4*)&Qs[r][d4] = make_float4(t.x * 0.125f, t.y * 0.125f,
                                           t.z * 0.125f, t.w * 0.125f);
    }

    float m0r = -INFINITY, m1r = -INFINITY, l0 = 0.f, l1 = 0.f;
    float o[8][4];
#pragma unroll
    for (int nd = 0; nd < 8; nd++)
#pragma unroll
        for (int e = 0; e < 4; e++) o[nd][e] = 0.f;

    for (int kt = 0; kt < nkt; kt++) {
        const int buf = kt & 1;
        const int kb = kt * 128;
        CP_WAIT0();
        __syncthreads();
        if (kt + 1 < nkt) {
            const int nb = buf ^ 1, ko = (kt + 1) * 128;
#pragma unroll
            for (int i = 0; i < 8; i++) {
                int idx = tid + i * 256;
                int r = idx >> 4, s = (idx & 15) * 4;
                cpa16(smK + (nb * 128 + r) * 68 + s, kp + (size_t)(ko + r) * HD_ + s);
                cpa16(smV + (nb * 128 + r) * 72 + s, vp + (size_t)(ko + r) * HD_ + s);
            }
        }
        CP_COMMIT();
        const float* Kb = smK + buf * 128 * 68;
        const float* Vb = smV + buf * 128 * 72;

        // ---- QK^T: 16 rows x 128 keys, keys column-permuted by pi ----
        float sf[16][4];
#pragma unroll
        for (int ni = 0; ni < 16; ni++)
#pragma unroll
            for (int e = 0; e < 4; e++) sf[ni][e] = 0.f;

#pragma unroll
        for (int ks = 0; ks < 8; ks++) {
            const int k = ks * 8 + qc;
            const float* ar = Qs[w * 16 + qr];
            uint32_t a0 = __float_as_uint(ar[k]);
            uint32_t a1 = __float_as_uint(ar[8 * 68 + k]);
            uint32_t a2 = __float_as_uint(ar[k + 4]);
            uint32_t a3 = __float_as_uint(ar[8 * 68 + k + 4]);
#pragma unroll
            for (int ni = 0; ni < 16; ni++) {
                const float* kr = Kb + (ni * 8 + piq) * 68;
                uint32_t b0 = __float_as_uint(kr[k]);
                uint32_t b1 = __float_as_uint(kr[k + 4]);
                mma_tf32(sf[ni], a0, a1, a2, a3, b0, b1);
            }
        }

        // ---- row max (masked only on diagonal / len-boundary tiles) ----
        const int rl = qbase + w * 16 + qr, rh = rl + 8;
        float mx0 = -INFINITY, mx1 = -INFINITY;
        if (kt == qt || kb + 128 > len) {
#pragma unroll
            for (int ni = 0; ni < 16; ni++) {
                int k0 = kb + ni * 8 + qc, k1 = k0 + 4;
                if (k0 > rl || k0 >= len) sf[ni][0] = -INFINITY;
                if (k1 > rl || k1 >= len) sf[ni][1] = -INFINITY;
                if (k0 > rh || k0 >= len) sf[ni][2] = -INFINITY;
                if (k1 > rh || k1 >= len) sf[ni][3] = -INFINITY;
                mx0 = fmaxf(mx0, fmaxf(sf[ni][0], sf[ni][1]));
                mx1 = fmaxf(mx1, fmaxf(sf[ni][2], sf[ni][3]));
            }
        } else {
#pragma unroll
            for (int ni = 0; ni < 16; ni++) {
                mx0 = fmaxf(mx0, fmaxf(sf[ni][0], sf[ni][1]));
                mx1 = fmaxf(mx1, fmaxf(sf[ni][2], sf[ni][3]));
            }
        }
        mx0 = fmaxf(mx0, __shfl_xor_sync(0xffffffffu, mx0, 1));
        mx0 = fmaxf(mx0, __shfl_xor_sync(0xffffffffu, mx0, 2));
        mx1 = fmaxf(mx1, __shfl_xor_sync(0xffffffffu, mx1, 1));
        mx1 = fmaxf(mx1, __shfl_xor_sync(0xffffffffu, mx1, 2));

        float mn0 = fmaxf(m0r, mx0), mn1 = fmaxf(m1r, mx1);
        float corr0 = __expf(m0r - mn0), corr1 = __expf(m1r - mn1);
        m0r = mn0; m1r = mn1;

        // ---- exp + row sum; P (tf32-rounded) kept in sf regs ----
        float s0 = 0.f, s1 = 0.f;
#pragma unroll
        for (int ni = 0; ni < 16; ni++) {
            float p0 = __expf(sf[ni][0] - mn0);
            float p1 = __expf(sf[ni][1] - mn0);
            float p2 = __expf(sf[ni][2] - mn1);
            float p3 = __expf(sf[ni][3] - mn1);
            s0 += p0 + p1; s1 += p2 + p3;
            sf[ni][0] = tf32r(p0); sf[ni][1] = tf32r(p1);
            sf[ni][2] = tf32r(p2); sf[ni][3] = tf32r(p3);
        }
        s0 += __shfl_xor_sync(0xffffffffu, s0, 1);
        s0 += __shfl_xor_sync(0xffffffffu, s0, 2);
        s1 += __shfl_xor_sync(0xffffffffu, s1, 1);
        s1 += __shfl_xor_sync(0xffffffffu, s1, 2);
        l0 = l0 * corr0 + s0;
        l1 = l1 * corr1 + s1;
#pragma unroll
        for (int nd = 0; nd < 8; nd++) {
            o[nd][0] *= corr0; o[nd][1] *= corr0;
            o[nd][2] *= corr1; o[nd][3] *= corr1;
        }

        // ---- O += P V: A-fragment straight from score regs (pi trick) ----
#pragma unroll
        for (int ks2 = 0; ks2 < 16; ks2++) {
            uint32_t a0 = __float_as_uint(sf[ks2][0]);   // (row qr,  key qc)
            uint32_t a1 = __float_as_uint(sf[ks2][2]);   // (row qr+8,key qc)
            uint32_t a2 = __float_as_uint(sf[ks2][1]);   // (row qr,  key qc+4)
            uint32_t a3 = __float_as_uint(sf[ks2][3]);   // (row qr+8,key qc+4)
            const float* v0 = Vb + (ks2 * 8 + qc) * 72;
            const float* v1 = v0 + 4 * 72;
#pragma unroll
            for (int nd = 0; nd < 8; nd++) {
                int dcol = nd * 8 + qr;
                uint32_t b0 = __float_as_uint(v0[dcol]);
                uint32_t b1 = __float_as_uint(v1[dcol]);
                mma_tf32(o[nd], a0, a1, a2, a3, b0, b1);
            }
        }
    }

    // ---- normalize + write tf32-rounded (feeds out-proj GEMM) ----
    const float inv0 = 1.f / l0, inv1 = 1.f / l1;
    const int rl = qbase + w * 16 + qr;
#pragma unroll
    for (int nd = 0; nd < 8; nd++) {
        int c = h * HD_ + nd * 8 + qc * 2;
        *(float2*)&g_attn[((size_t)b * S_ + rl) * TD_ + c] =
            make_float2(tf32r(o[nd][0] * inv0), tf32r(o[nd][1] * inv0));
        *(float2*)&g_attn[((size_t)b * S_ + rl + 8) * TD_ + c] =
            make_float2(tf32r(o[nd][2] * inv1), tf32r(o[nd][3] * inv1));
    }
}

// ---------------- launch ----------------
extern "C" void kernel_launch(void* const* d_in, const int* in_sizes, int n_in,
                              void* d_out, int out_size) {
    const float* query = (const float*)d_in[0];
    const float* W_in  = (const float*)d_in[1];
    const float* W_out = (const float*)d_in[2];
    const float* sinb  = (const float*)d_in[3];
    const float* cosb  = (const float*)d_in[4];
    const unsigned char* mask = (const unsigned char*)d_in[5];
    float* out = (float*)d_out;

    void *p_qkv = nullptr, *p_attn = nullptr, *p_qt = nullptr, *p_wi = nullptr, *p_wo = nullptr;
    cudaGetSymbolAddress(&p_qkv, g_qkv);
    cudaGetSymbolAddress(&p_attn, g_attn);
    cudaGetSymbolAddress(&p_qt, g_qt);
    cudaGetSymbolAddress(&p_wi, g_wi);
    cudaGetSymbolAddress(&p_wo, g_wo);
    cudaFuncSetAttribute(attn_tf32, cudaFuncAttributeMaxDynamicSharedMemorySize,
                         ATTN_SMEM_BYTES);
    cudaFuncSetAttribute(gemm_tf32, cudaFuncAttributeMaxDynamicSharedMemorySize,
                         GEMM_SMEM_BYTES);

    lengths_kernel<<<1, 256>>>(mask);

    // pre-round GEMM inputs to tf32 (once; removes all in-loop cvt)
    cvt_tf32<<<(B_ * S_ * DM_ / 4 + 255) / 256, 256>>>(query, (float*)p_qt, B_ * S_ * DM_ / 4);
    cvt_tf32<<<(3 * TD_ * DM_ / 4 + 255) / 256, 256>>>(W_in, (float*)p_wi, 3 * TD_ * DM_ / 4);
    cvt_tf32<<<(DM_ * TD_ / 4 + 255) / 256, 256>>>(W_out, (float*)p_wo, DM_ * TD_ / 4);

    // QKV projection: [4096,1024] x [3072,1024]^T -> [4096,3072]
    gemm_tf32<<<dim3(3 * TD_ / 128, B_ * S_ / 128), 256, GEMM_SMEM_BYTES>>>(
        (const float*)p_qt, (const float*)p_wi, (float*)p_qkv, B_ * S_, 3 * TD_, DM_);

    // RoPE + scatter to [B,H,S,HD] (tf32-rounded)
    rope_kernel<<<(B_ * S_ * H_ * HD_) / 256, 256>>>(sinb, cosb);

    // causal flash attention (tf32 tensor-core)
    attn_tf32<<<dim3(S_ / 128, B_ * H_), 256, ATTN_SMEM_BYTES>>>();

    // output projection: [4096,1024] x [1024,1024]^T -> d_out
    gemm_tf32<<<dim3(DM_ / 128, B_ * S_ / 128), 256, GEMM_SMEM_BYTES>>>(
        (const float*)p_attn, (const float*)p_wo, out, B_ * S_, DM_, TD_);
}